// round 3
// baseline (speedup 1.0000x reference)
#include <cuda_runtime.h>
#include <cuda_bf16.h>
#include <cstdint>

// PaiNN conv: ds (N,64), dv (N,3,64) concatenated in d_out.
// Inputs: 0 node(N,64) 1 equivariant(N,3,64) 2 rbf(E,20) 3 envelope(E,1)
//         4 r_ij(E,3) 5 edge_index(E,2) i64/i32  6 Ws(64,64) 7 bs(64)
//         8 Wphi(192,64) 9 bphi(192) 10 Ww(192,20) 11 bw(192)

#define U 64
#define S3 192
#define R 20
#define MAXN 50000
#define MAXE 800000
#define NPB 8
#define CH 16

__device__ float g_s[(size_t)MAXN * S3];
__device__ int   g_idx_is64;
__device__ int   g_cnt[MAXN];
__device__ int   g_scan[MAXN];
__device__ int   g_bsum[64];
__device__ int   g_off[MAXN + 1];
__device__ int   g_run[MAXN];
__device__ int2  g_perm[MAXE];

// ---------------- packed f32x2 helpers ----------------
__device__ __forceinline__ unsigned long long pk2(float lo, float hi) {
    unsigned long long r;
    asm("mov.b64 %0, {%1, %2};" : "=l"(r) : "f"(lo), "f"(hi));
    return r;
}
__device__ __forceinline__ unsigned long long fma2(unsigned long long a,
                                                   unsigned long long b,
                                                   unsigned long long c) {
    unsigned long long d;
    asm("fma.rn.f32x2 %0, %1, %2, %3;" : "=l"(d) : "l"(a), "l"(b), "l"(c));
    return d;
}
__device__ __forceinline__ float upk_sum(unsigned long long a) {
    float lo, hi;
    asm("mov.b64 {%0, %1}, %2;" : "=f"(lo), "=f"(hi) : "l"(a));
    return lo + hi;
}

// ---------------- idx dtype detector ----------------
__global__ void detect_idx_kernel(const int* __restrict__ eidx32, int n_edges) {
    __shared__ int warp_or[8];
    int v = 0;
    int limit = n_edges < 4096 ? n_edges : 4096;
    for (int k = threadIdx.x; k < limit; k += blockDim.x)
        v |= eidx32[2 * k + 1];
    for (int o = 16; o > 0; o >>= 1)
        v |= __shfl_xor_sync(0xffffffffu, v, o);
    if ((threadIdx.x & 31) == 0) warp_or[threadIdx.x >> 5] = v;
    __syncthreads();
    if (threadIdx.x == 0) {
        int r = 0;
        for (int w = 0; w < (int)(blockDim.x >> 5); w++) r |= warp_or[w];
        g_idx_is64 = (r == 0) ? 1 : 0;
    }
}

__global__ void zero_cnt_kernel(int n_nodes) {
    int i = blockIdx.x * blockDim.x + threadIdx.x;
    if (i < n_nodes) g_cnt[i] = 0;
}

__global__ void hist_kernel(const void* __restrict__ eidx, int n_edges) {
    const bool is64 = (g_idx_is64 != 0);
    for (int e = blockIdx.x * blockDim.x + threadIdx.x; e < n_edges;
         e += gridDim.x * blockDim.x) {
        int dst = is64 ? (int)((const long long*)eidx)[2 * (size_t)e]
                       : ((const int*)eidx)[2 * (size_t)e];
        atomicAdd(&g_cnt[dst], 1);
    }
}

__global__ void scan1_kernel(int n_nodes) {
    __shared__ int sh[1024];
    int tid = threadIdx.x;
    int i = blockIdx.x * 1024 + tid;
    int v = (i < n_nodes) ? g_cnt[i] : 0;
    sh[tid] = v;
    __syncthreads();
    for (int off = 1; off < 1024; off <<= 1) {
        int t = (tid >= off) ? sh[tid - off] : 0;
        __syncthreads();
        sh[tid] += t;
        __syncthreads();
    }
    if (i < n_nodes) g_scan[i] = sh[tid] - v;
    if (tid == 1023) g_bsum[blockIdx.x] = sh[1023];
}

__global__ void scan2_kernel(int nb) {
    if (threadIdx.x == 0 && blockIdx.x == 0) {
        int s = 0;
        for (int b = 0; b < nb; b++) {
            int t = g_bsum[b];
            g_bsum[b] = s;
            s += t;
        }
    }
}

__global__ void scan3_kernel(int n_nodes, int n_edges) {
    int i = blockIdx.x * blockDim.x + threadIdx.x;
    if (i < n_nodes) {
        int off = g_scan[i] + g_bsum[i >> 10];
        g_off[i] = off;
        g_run[i] = off;
    }
    if (i == 0) g_off[n_nodes] = n_edges;
}

__global__ void scatter_kernel(const void* __restrict__ eidx, int n_edges) {
    const bool is64 = (g_idx_is64 != 0);
    for (int e = blockIdx.x * blockDim.x + threadIdx.x; e < n_edges;
         e += gridDim.x * blockDim.x) {
        int dst, j;
        if (is64) {
            const long long* p = (const long long*)eidx;
            dst = (int)p[2 * (size_t)e];
            j = (int)p[2 * (size_t)e + 1];
        } else {
            const int* p = (const int*)eidx;
            dst = p[2 * (size_t)e];
            j = p[2 * (size_t)e + 1];
        }
        int pos = atomicAdd(&g_run[dst], 1);
        g_perm[pos] = make_int2(e, j);
    }
}

// ---------------- node MLP ----------------
#define WPAD 68
#define SMEM_MLP ((64 * WPAD + 192 * WPAD + 64 + 192 + NPB * 64 + NPB * 64) * 4)

__global__ void mlp_kernel(const float* __restrict__ node,
                           const float* __restrict__ Ws, const float* __restrict__ bs,
                           const float* __restrict__ Wphi, const float* __restrict__ bphi,
                           int n_nodes) {
    extern __shared__ float sh[];
    float* sWs   = sh;
    float* sWphi = sWs + 64 * WPAD;
    float* sbs   = sWphi + 192 * WPAD;
    float* sbphi = sbs + 64;
    float* snode = sbphi + 192;
    float* shh   = snode + NPB * 64;

    for (int x = threadIdx.x; x < 64 * 64; x += blockDim.x)
        sWs[(x >> 6) * WPAD + (x & 63)] = Ws[x];
    for (int x = threadIdx.x; x < 192 * 64; x += blockDim.x)
        sWphi[(x >> 6) * WPAD + (x & 63)] = Wphi[x];
    for (int x = threadIdx.x; x < 64; x += blockDim.x)  sbs[x] = bs[x];
    for (int x = threadIdx.x; x < 192; x += blockDim.x) sbphi[x] = bphi[x];
    __syncthreads();

    int ngroups = (n_nodes + NPB - 1) / NPB;
    for (int g = blockIdx.x; g < ngroups; g += gridDim.x) {
        int n0 = g * NPB;
        __syncthreads();
        for (int x = threadIdx.x; x < NPB * 64; x += blockDim.x) {
            int n = x >> 6, k = x & 63;
            snode[x] = (n0 + n < n_nodes) ? node[(size_t)(n0 + n) * 64 + k] : 0.f;
        }
        __syncthreads();
        for (int t = threadIdx.x; t < NPB * 64; t += blockDim.x) {
            int n = t >> 6, cc = t & 63;
            const ulonglong2* wp = (const ulonglong2*)&sWs[cc * WPAD];
            const ulonglong2* np = (const ulonglong2*)&snode[n * 64];
            unsigned long long acc = pk2(sbs[cc], 0.f);
#pragma unroll
            for (int q = 0; q < 16; q++) {
                ulonglong2 a = wp[q];
                ulonglong2 b = np[q];
                acc = fma2(a.x, b.x, acc);
                acc = fma2(a.y, b.y, acc);
            }
            float v = upk_sum(acc);
            float sg = 1.f / (1.f + __expf(-v));
            shh[t] = v * sg;
        }
        __syncthreads();
        for (int t = threadIdx.x; t < NPB * S3; t += blockDim.x) {
            int n = t / S3, cc = t % S3;
            const ulonglong2* wp = (const ulonglong2*)&sWphi[cc * WPAD];
            const ulonglong2* hp = (const ulonglong2*)&shh[n * 64];
            unsigned long long acc = pk2(sbphi[cc], 0.f);
#pragma unroll
            for (int q = 0; q < 16; q++) {
                ulonglong2 a = wp[q];
                ulonglong2 b = hp[q];
                acc = fma2(a.x, b.x, acc);
                acc = fma2(a.y, b.y, acc);
            }
            if (n0 + n < n_nodes)
                g_s[(size_t)(n0 + n) * S3 + cc] = upk_sum(acc);
        }
    }
}

// ---------------- node-centric aggregation, 256 threads / node ----------------
// threads 0..191: radial channel c (10 packed weight regs each) -> sw to shared
// all 256 threads: output element (comp = tid>>6: 0=ds, 1..3=dv rows; ch=tid&63)
__global__ void __launch_bounds__(256)
node_kernel(const float* __restrict__ rbf, const float* __restrict__ env,
            const float* __restrict__ rij,
            const float* __restrict__ Ww, const float* __restrict__ bw,
            const float* __restrict__ equiv,
            float* __restrict__ out_ds, float* __restrict__ out_dv,
            int n_nodes) {
    __shared__ __align__(8)  float sh_rbf[CH][R];
    __shared__ float sh_env[CH];
    __shared__ float sh_rij[CH][3];
    __shared__ int   sh_e[CH];
    __shared__ int   sh_j[CH];
    __shared__ __align__(16) float sh_sw[CH][S3];

    const int tid  = threadIdx.x;
    const int ch   = tid & 63;
    const int comp = tid >> 6;   // 0..3
    const int c    = tid;        // radial channel if < 192

    unsigned long long wwp[10];
    float bwv = 0.f;
    if (c < S3) {
        const float* wr = Ww + (size_t)c * R;
#pragma unroll
        for (int k = 0; k < 10; k++) wwp[k] = pk2(wr[2 * k], wr[2 * k + 1]);
        bwv = bw[c];
    }

    for (int i = blockIdx.x; i < n_nodes; i += gridDim.x) {
        const int start = g_off[i], end = g_off[i + 1];
        float acc = 0.f;

        for (int base = start; base < end; base += CH) {
            const int cnt = min(CH, end - base);
            __syncthreads();  // guard shared reuse (prev tile phase C done)
            if (tid < cnt) {
                int2 ej = g_perm[base + tid];
                int e = ej.x;
                sh_e[tid] = e;
                sh_j[tid] = ej.y;
                sh_env[tid] = env[e];
                sh_rij[tid][0] = rij[3 * (size_t)e];
                sh_rij[tid][1] = rij[3 * (size_t)e + 1];
                sh_rij[tid][2] = rij[3 * (size_t)e + 2];
            }
            __syncthreads();
            for (int x = tid; x < cnt * R; x += 256) {
                int el = x / R, k = x - el * R;
                sh_rbf[el][k] = rbf[(size_t)sh_e[el] * R + k];
            }
            __syncthreads();

            // phase B: sw[el][c] = s[j][c] * (rbf[el].Ww_c + bw_c) * env
            if (c < S3) {
#pragma unroll 4
                for (int el = 0; el < cnt; el++) {
                    int j = sh_j[el];
                    float s = g_s[(size_t)j * S3 + c];  // coalesced gather
                    const unsigned long long* rb =
                        (const unsigned long long*)sh_rbf[el];
                    unsigned long long a0 = pk2(bwv, 0.f);
                    unsigned long long a1 = pk2(0.f, 0.f);
#pragma unroll
                    for (int k = 0; k < 10; k += 2) {
                        a0 = fma2(rb[k],     wwp[k],     a0);
                        a1 = fma2(rb[k + 1], wwp[k + 1], a1);
                    }
                    float w = (upk_sum(a0) + upk_sum(a1)) * sh_env[el];
                    sh_sw[el][c] = s * w;
                }
            }
            __syncthreads();

            // phase C: each thread accumulates its single output element
            if (comp == 0) {
#pragma unroll 4
                for (int el = 0; el < cnt; el++)
                    acc += sh_sw[el][ch];
            } else {
                const int d = comp - 1;
#pragma unroll 4
                for (int el = 0; el < cnt; el++) {
                    int j = sh_j[el];
                    float vj = equiv[((size_t)j * 3 + d) * U + ch];  // coalesced
                    float sw1 = sh_sw[el][64 + ch];
                    float sw2 = sh_sw[el][128 + ch];
                    acc = fmaf(vj, sw1, fmaf(sh_rij[el][d], sw2, acc));
                }
            }
        }

        if (comp == 0)
            out_ds[(size_t)i * U + ch] = acc;
        else
            out_dv[((size_t)i * 3 + (comp - 1)) * U + ch] = acc;
    }
}

// ---------------------------------------------------------------------------
extern "C" void kernel_launch(void* const* d_in, const int* in_sizes, int n_in,
                              void* d_out, int out_size) {
    const float* node  = (const float*)d_in[0];
    const float* equiv = (const float*)d_in[1];
    const float* rbf   = (const float*)d_in[2];
    const float* env   = (const float*)d_in[3];
    const float* rij   = (const float*)d_in[4];
    const void*  eidx  = d_in[5];
    const float* Ws    = (const float*)d_in[6];
    const float* bs    = (const float*)d_in[7];
    const float* Wphi  = (const float*)d_in[8];
    const float* bphi  = (const float*)d_in[9];
    const float* Ww    = (const float*)d_in[10];
    const float* bw    = (const float*)d_in[11];

    int n_nodes = in_sizes[0] / U;
    int n_edges = in_sizes[3];

    float* out_ds = (float*)d_out;
    float* out_dv = out_ds + (size_t)n_nodes * U;

    int nb_scan = (n_nodes + 1023) / 1024;

    detect_idx_kernel<<<1, 256>>>((const int*)eidx, n_edges);
    zero_cnt_kernel<<<(n_nodes + 255) / 256, 256>>>(n_nodes);

    cudaFuncSetAttribute(mlp_kernel, cudaFuncAttributeMaxDynamicSharedMemorySize, SMEM_MLP);
    mlp_kernel<<<592, 256, SMEM_MLP>>>(node, Ws, bs, Wphi, bphi, n_nodes);

    hist_kernel<<<400, 256>>>(eidx, n_edges);
    scan1_kernel<<<nb_scan, 1024>>>(n_nodes);
    scan2_kernel<<<1, 32>>>(nb_scan);
    scan3_kernel<<<(n_nodes + 1023) / 1024, 1024>>>(n_nodes, n_edges);
    scatter_kernel<<<400, 256>>>(eidx, n_edges);

    node_kernel<<<1184, 256>>>(rbf, env, rij, Ww, bw, equiv,
                               out_ds, out_dv, n_nodes);
}

// round 4
// speedup vs baseline: 1.2037x; 1.2037x over previous
#include <cuda_runtime.h>
#include <cuda_bf16.h>
#include <cstdint>

// PaiNN conv: ds (N,64), dv (N,3,64) concatenated in d_out.
// Inputs: 0 node(N,64) 1 equivariant(N,3,64) 2 rbf(E,20) 3 envelope(E,1)
//         4 r_ij(E,3) 5 edge_index(E,2) i64/i32  6 Ws(64,64) 7 bs(64)
//         8 Wphi(192,64) 9 bphi(192) 10 Ww(192,20) 11 bw(192)

#define U 64
#define S3 192
#define R 20
#define MAXN 50000
#define MAXE 800000
#define NPB 8
#define CE 32
#define NB 1184

__device__ float g_s[(size_t)MAXN * S3];
__device__ int   g_idx_is64;
__device__ int   g_cnt[MAXN];
__device__ int   g_scan[MAXN];
__device__ int   g_bsum[64];
__device__ int   g_off[MAXN + 1];
__device__ int   g_run[MAXN];
__device__ int4  g_perm[MAXE];   // (e, j, dst, 0)

// ---------------- packed f32x2 helpers ----------------
__device__ __forceinline__ unsigned long long pk2(float lo, float hi) {
    unsigned long long r;
    asm("mov.b64 %0, {%1, %2};" : "=l"(r) : "f"(lo), "f"(hi));
    return r;
}
__device__ __forceinline__ unsigned long long fma2(unsigned long long a,
                                                   unsigned long long b,
                                                   unsigned long long c) {
    unsigned long long d;
    asm("fma.rn.f32x2 %0, %1, %2, %3;" : "=l"(d) : "l"(a), "l"(b), "l"(c));
    return d;
}
__device__ __forceinline__ float upk_sum(unsigned long long a) {
    float lo, hi;
    asm("mov.b64 {%0, %1}, %2;" : "=f"(lo), "=f"(hi) : "l"(a));
    return lo + hi;
}
__device__ __forceinline__ void red_add(float* p, float v) {
    asm volatile("red.global.add.f32 [%0], %1;" :: "l"(p), "f"(v) : "memory");
}

// ---------------- idx dtype detector ----------------
__global__ void detect_idx_kernel(const int* __restrict__ eidx32, int n_edges) {
    __shared__ int warp_or[8];
    int v = 0;
    int limit = n_edges < 4096 ? n_edges : 4096;
    for (int k = threadIdx.x; k < limit; k += blockDim.x)
        v |= eidx32[2 * k + 1];
    for (int o = 16; o > 0; o >>= 1)
        v |= __shfl_xor_sync(0xffffffffu, v, o);
    if ((threadIdx.x & 31) == 0) warp_or[threadIdx.x >> 5] = v;
    __syncthreads();
    if (threadIdx.x == 0) {
        int r = 0;
        for (int w = 0; w < (int)(blockDim.x >> 5); w++) r |= warp_or[w];
        g_idx_is64 = (r == 0) ? 1 : 0;
    }
}

__global__ void zero_cnt_kernel(int n_nodes) {
    int i = blockIdx.x * blockDim.x + threadIdx.x;
    if (i < n_nodes) g_cnt[i] = 0;
}

__global__ void zero_out_kernel(float* __restrict__ out, long long n) {
    long long n4 = n >> 2;
    float4 z = make_float4(0.f, 0.f, 0.f, 0.f);
    float4* o4 = (float4*)out;
    for (long long i = (long long)blockIdx.x * blockDim.x + threadIdx.x; i < n4;
         i += (long long)gridDim.x * blockDim.x)
        o4[i] = z;
    long long base = n4 << 2;
    for (long long i = base + (long long)blockIdx.x * blockDim.x + threadIdx.x; i < n;
         i += (long long)gridDim.x * blockDim.x)
        out[i] = 0.f;
}

__global__ void hist_kernel(const void* __restrict__ eidx, int n_edges) {
    const bool is64 = (g_idx_is64 != 0);
    for (int e = blockIdx.x * blockDim.x + threadIdx.x; e < n_edges;
         e += gridDim.x * blockDim.x) {
        int dst = is64 ? (int)((const long long*)eidx)[2 * (size_t)e]
                       : ((const int*)eidx)[2 * (size_t)e];
        atomicAdd(&g_cnt[dst], 1);
    }
}

__global__ void scan1_kernel(int n_nodes) {
    __shared__ int sh[1024];
    int tid = threadIdx.x;
    int i = blockIdx.x * 1024 + tid;
    int v = (i < n_nodes) ? g_cnt[i] : 0;
    sh[tid] = v;
    __syncthreads();
    for (int off = 1; off < 1024; off <<= 1) {
        int t = (tid >= off) ? sh[tid - off] : 0;
        __syncthreads();
        sh[tid] += t;
        __syncthreads();
    }
    if (i < n_nodes) g_scan[i] = sh[tid] - v;
    if (tid == 1023) g_bsum[blockIdx.x] = sh[1023];
}

__global__ void scan2_kernel(int nb) {
    if (threadIdx.x == 0 && blockIdx.x == 0) {
        int s = 0;
        for (int b = 0; b < nb; b++) {
            int t = g_bsum[b];
            g_bsum[b] = s;
            s += t;
        }
    }
}

__global__ void scan3_kernel(int n_nodes, int n_edges) {
    int i = blockIdx.x * blockDim.x + threadIdx.x;
    if (i < n_nodes) {
        int off = g_scan[i] + g_bsum[i >> 10];
        g_off[i] = off;
        g_run[i] = off;
    }
    if (i == 0) g_off[n_nodes] = n_edges;
}

__global__ void scatter_kernel(const void* __restrict__ eidx, int n_edges) {
    const bool is64 = (g_idx_is64 != 0);
    for (int e = blockIdx.x * blockDim.x + threadIdx.x; e < n_edges;
         e += gridDim.x * blockDim.x) {
        int dst, j;
        if (is64) {
            const long long* p = (const long long*)eidx;
            dst = (int)p[2 * (size_t)e];
            j = (int)p[2 * (size_t)e + 1];
        } else {
            const int* p = (const int*)eidx;
            dst = p[2 * (size_t)e];
            j = p[2 * (size_t)e + 1];
        }
        int pos = atomicAdd(&g_run[dst], 1);
        g_perm[pos] = make_int4(e, j, dst, 0);
    }
}

// ---------------- node MLP ----------------
#define WPAD 68
#define SMEM_MLP ((64 * WPAD + 192 * WPAD + 64 + 192 + NPB * 64 + NPB * 64) * 4)

__global__ void mlp_kernel(const float* __restrict__ node,
                           const float* __restrict__ Ws, const float* __restrict__ bs,
                           const float* __restrict__ Wphi, const float* __restrict__ bphi,
                           int n_nodes) {
    extern __shared__ float sh[];
    float* sWs   = sh;
    float* sWphi = sWs + 64 * WPAD;
    float* sbs   = sWphi + 192 * WPAD;
    float* sbphi = sbs + 64;
    float* snode = sbphi + 192;
    float* shh   = snode + NPB * 64;

    for (int x = threadIdx.x; x < 64 * 64; x += blockDim.x)
        sWs[(x >> 6) * WPAD + (x & 63)] = Ws[x];
    for (int x = threadIdx.x; x < 192 * 64; x += blockDim.x)
        sWphi[(x >> 6) * WPAD + (x & 63)] = Wphi[x];
    for (int x = threadIdx.x; x < 64; x += blockDim.x)  sbs[x] = bs[x];
    for (int x = threadIdx.x; x < 192; x += blockDim.x) sbphi[x] = bphi[x];
    __syncthreads();

    int ngroups = (n_nodes + NPB - 1) / NPB;
    for (int g = blockIdx.x; g < ngroups; g += gridDim.x) {
        int n0 = g * NPB;
        __syncthreads();
        for (int x = threadIdx.x; x < NPB * 64; x += blockDim.x) {
            int n = x >> 6, k = x & 63;
            snode[x] = (n0 + n < n_nodes) ? node[(size_t)(n0 + n) * 64 + k] : 0.f;
        }
        __syncthreads();
        for (int t = threadIdx.x; t < NPB * 64; t += blockDim.x) {
            int n = t >> 6, cc = t & 63;
            const ulonglong2* wp = (const ulonglong2*)&sWs[cc * WPAD];
            const ulonglong2* np = (const ulonglong2*)&snode[n * 64];
            unsigned long long acc = pk2(sbs[cc], 0.f);
#pragma unroll
            for (int q = 0; q < 16; q++) {
                ulonglong2 a = wp[q];
                ulonglong2 b = np[q];
                acc = fma2(a.x, b.x, acc);
                acc = fma2(a.y, b.y, acc);
            }
            float v = upk_sum(acc);
            float sg = 1.f / (1.f + __expf(-v));
            shh[t] = v * sg;
        }
        __syncthreads();
        for (int t = threadIdx.x; t < NPB * S3; t += blockDim.x) {
            int n = t / S3, cc = t % S3;
            const ulonglong2* wp = (const ulonglong2*)&sWphi[cc * WPAD];
            const ulonglong2* hp = (const ulonglong2*)&shh[n * 64];
            unsigned long long acc = pk2(sbphi[cc], 0.f);
#pragma unroll
            for (int q = 0; q < 16; q++) {
                ulonglong2 a = wp[q];
                ulonglong2 b = hp[q];
                acc = fma2(a.x, b.x, acc);
                acc = fma2(a.y, b.y, acc);
            }
            if (n0 + n < n_nodes)
                g_s[(size_t)(n0 + n) * S3 + cc] = upk_sum(acc);
        }
    }
}

// ---------------- sweep kernel: contiguous dst-sorted edge ranges ----------------
// 256 threads. Phase B: thread c<192 owns radial channel c (weights in regs).
// Phase C: thread = output element (comp=tid>>6: 0=ds, 1..3=dv), run-carry
//          accumulator flushed via red.global.add.f32 at node boundaries.
__global__ void __launch_bounds__(256)
sweep_kernel(const float* __restrict__ rbf, const float* __restrict__ env,
             const float* __restrict__ rij,
             const float* __restrict__ Ww, const float* __restrict__ bw,
             const float* __restrict__ equiv,
             float* __restrict__ out_ds, float* __restrict__ out_dv,
             int n_edges) {
    __shared__ __align__(16) float sh_rbf[CE][R];
    __shared__ float sh_env[CE];
    __shared__ float sh_rij[CE][3];
    __shared__ int   sh_e[CE];
    __shared__ int   sh_j[CE];
    __shared__ int   sh_i[CE];
    __shared__ __align__(16) float sh_sw[CE][S3];

    const int tid  = threadIdx.x;
    const int ch   = tid & 63;
    const int comp = tid >> 6;   // 0..3
    const int c    = tid;        // radial channel if < 192
    const int d    = comp - 1;

    unsigned long long wwp[10];
    float bwv = 0.f;
    if (c < S3) {
        const float* wr = Ww + (size_t)c * R;
#pragma unroll
        for (int k = 0; k < 10; k++) wwp[k] = pk2(wr[2 * k], wr[2 * k + 1]);
        bwv = bw[c];
    }

    const int begin = (int)(((long long)n_edges * blockIdx.x) / gridDim.x);
    const int bend  = (int)(((long long)n_edges * (blockIdx.x + 1)) / gridDim.x);

    int   cur = -1;
    float acc = 0.f;

    for (int base = begin; base < bend; base += CE) {
        const int cnt = min(CE, bend - base);
        __syncthreads();  // prev phase C done before staging
        if (tid < cnt) {
            int4 p = g_perm[base + tid];
            sh_e[tid] = p.x;
            sh_j[tid] = p.y;
            sh_i[tid] = p.z;
            sh_env[tid] = env[p.x];
            sh_rij[tid][0] = rij[3 * (size_t)p.x];
            sh_rij[tid][1] = rij[3 * (size_t)p.x + 1];
            sh_rij[tid][2] = rij[3 * (size_t)p.x + 2];
        }
        __syncthreads();
        for (int x = tid; x < cnt * R; x += 256) {
            int el = x / R, k = x - el * R;
            sh_rbf[el][k] = rbf[(size_t)sh_e[el] * R + k];
        }
        __syncthreads();

        // phase B: sw[el][c] = s[j][c] * ((rbf . Ww_c + bw_c) * env)
        if (c < S3) {
#pragma unroll 4
            for (int el = 0; el < cnt; el++) {
                int j = sh_j[el];
                float s = g_s[(size_t)j * S3 + c];  // coalesced 128B/warp
                const ulonglong2* rb = (const ulonglong2*)sh_rbf[el];
                unsigned long long a0 = pk2(bwv, 0.f);
                unsigned long long a1 = pk2(0.f, 0.f);
#pragma unroll
                for (int q = 0; q < 5; q++) {
                    ulonglong2 t = rb[q];     // LDS.128 broadcast -> 2 packed pairs
                    a0 = fma2(t.x, wwp[2 * q],     a0);
                    a1 = fma2(t.y, wwp[2 * q + 1], a1);
                }
                float w = (upk_sum(a0) + upk_sum(a1)) * sh_env[el];
                sh_sw[el][c] = s * w;
            }
        }
        __syncthreads();

        // phase C: run-carry segmented accumulation
        if (comp == 0) {
#pragma unroll 4
            for (int el = 0; el < cnt; el++) {
                int ni = sh_i[el];
                if (ni != cur) {
                    if (cur >= 0) red_add(out_ds + (size_t)cur * U + ch, acc);
                    acc = 0.f;
                    cur = ni;
                }
                acc += sh_sw[el][ch];
            }
        } else {
#pragma unroll 4
            for (int el = 0; el < cnt; el++) {
                int j = sh_j[el];
                float vj = equiv[((size_t)j * 3 + d) * U + ch];  // coalesced
                int ni = sh_i[el];
                if (ni != cur) {
                    if (cur >= 0) red_add(out_dv + ((size_t)cur * 3 + d) * U + ch, acc);
                    acc = 0.f;
                    cur = ni;
                }
                acc = fmaf(vj, sh_sw[el][64 + ch],
                           fmaf(sh_rij[el][d], sh_sw[el][128 + ch], acc));
            }
        }
    }
    // final flush
    if (cur >= 0) {
        if (comp == 0) red_add(out_ds + (size_t)cur * U + ch, acc);
        else           red_add(out_dv + ((size_t)cur * 3 + d) * U + ch, acc);
    }
}

// ---------------------------------------------------------------------------
extern "C" void kernel_launch(void* const* d_in, const int* in_sizes, int n_in,
                              void* d_out, int out_size) {
    const float* node  = (const float*)d_in[0];
    const float* equiv = (const float*)d_in[1];
    const float* rbf   = (const float*)d_in[2];
    const float* env   = (const float*)d_in[3];
    const float* rij   = (const float*)d_in[4];
    const void*  eidx  = d_in[5];
    const float* Ws    = (const float*)d_in[6];
    const float* bs    = (const float*)d_in[7];
    const float* Wphi  = (const float*)d_in[8];
    const float* bphi  = (const float*)d_in[9];
    const float* Ww    = (const float*)d_in[10];
    const float* bw    = (const float*)d_in[11];

    int n_nodes = in_sizes[0] / U;
    int n_edges = in_sizes[3];

    float* out_ds = (float*)d_out;
    float* out_dv = out_ds + (size_t)n_nodes * U;

    int nb_scan = (n_nodes + 1023) / 1024;

    detect_idx_kernel<<<1, 256>>>((const int*)eidx, n_edges);
    zero_cnt_kernel<<<(n_nodes + 255) / 256, 256>>>(n_nodes);
    zero_out_kernel<<<592, 256>>>((float*)d_out, (long long)out_size);

    cudaFuncSetAttribute(mlp_kernel, cudaFuncAttributeMaxDynamicSharedMemorySize, SMEM_MLP);
    mlp_kernel<<<592, 256, SMEM_MLP>>>(node, Ws, bs, Wphi, bphi, n_nodes);

    hist_kernel<<<400, 256>>>(eidx, n_edges);
    scan1_kernel<<<nb_scan, 1024>>>(n_nodes);
    scan2_kernel<<<1, 32>>>(nb_scan);
    scan3_kernel<<<(n_nodes + 1023) / 1024, 1024>>>(n_nodes, n_edges);
    scatter_kernel<<<400, 256>>>(eidx, n_edges);

    sweep_kernel<<<NB, 256>>>(rbf, env, rij, Ww, bw, equiv,
                              out_ds, out_dv, n_edges);
}

// round 6
// speedup vs baseline: 1.3802x; 1.1467x over previous
#include <cuda_runtime.h>
#include <cuda_bf16.h>
#include <cstdint>

// PaiNN conv: ds (N,64), dv (N,3,64) concatenated in d_out.
// Inputs: 0 node(N,64) 1 equivariant(N,3,64) 2 rbf(E,20) 3 envelope(E,1)
//         4 r_ij(E,3) 5 edge_index(E,2) i64/i32  6 Ws(64,64) 7 bs(64)
//         8 Wphi(192,64) 9 bphi(192) 10 Ww(192,20) 11 bw(192)

#define U 64
#define S3 192
#define R 20
#define MAXN 50000
#define MAXE 800000
#define CE 32
#define EROW 28          // floats per edge record (112B)
#define NB 592
#define MT 64            // nodes per MLP tile

typedef unsigned long long ull;

__device__ float g_s[(size_t)MAXN * S3];
__device__ float g_edata[(size_t)MAXE * EROW];
__device__ int   g_idx_is64;
__device__ int   g_cnt[MAXN];
__device__ int   g_scan[MAXN];
__device__ int   g_bsum[64];
__device__ int   g_run[MAXN];

// ---------------- packed f32x2 helpers ----------------
__device__ __forceinline__ ull pk2(float lo, float hi) {
    ull r;
    asm("mov.b64 %0, {%1, %2};" : "=l"(r) : "f"(lo), "f"(hi));
    return r;
}
__device__ __forceinline__ ull fma2(ull a, ull b, ull c) {
    ull d;
    asm("fma.rn.f32x2 %0, %1, %2, %3;" : "=l"(d) : "l"(a), "l"(b), "l"(c));
    return d;
}
__device__ __forceinline__ void upk(ull a, float& lo, float& hi) {
    asm("mov.b64 {%0, %1}, %2;" : "=f"(lo), "=f"(hi) : "l"(a));
}
__device__ __forceinline__ float upk_sum(ull a) {
    float lo, hi;
    upk(a, lo, hi);
    return lo + hi;
}
__device__ __forceinline__ void red_add(float* p, float v) {
    asm volatile("red.global.add.f32 [%0], %1;" :: "l"(p), "f"(v) : "memory");
}

// ---------------- idx dtype detector ----------------
__global__ void detect_idx_kernel(const int* __restrict__ eidx32, int n_edges) {
    __shared__ int warp_or[8];
    int v = 0;
    int limit = n_edges < 4096 ? n_edges : 4096;
    for (int k = threadIdx.x; k < limit; k += blockDim.x)
        v |= eidx32[2 * k + 1];
    for (int o = 16; o > 0; o >>= 1)
        v |= __shfl_xor_sync(0xffffffffu, v, o);
    if ((threadIdx.x & 31) == 0) warp_or[threadIdx.x >> 5] = v;
    __syncthreads();
    if (threadIdx.x == 0) {
        int r = 0;
        for (int w = 0; w < (int)(blockDim.x >> 5); w++) r |= warp_or[w];
        g_idx_is64 = (r == 0) ? 1 : 0;
    }
}

__global__ void zero_cnt_kernel(int n_nodes) {
    int i = blockIdx.x * blockDim.x + threadIdx.x;
    if (i < n_nodes) g_cnt[i] = 0;
}

__global__ void zero_out_kernel(float* __restrict__ out, long long n) {
    long long n4 = n >> 2;
    float4 z = make_float4(0.f, 0.f, 0.f, 0.f);
    float4* o4 = (float4*)out;
    for (long long i = (long long)blockIdx.x * blockDim.x + threadIdx.x; i < n4;
         i += (long long)gridDim.x * blockDim.x)
        o4[i] = z;
    long long base = n4 << 2;
    for (long long i = base + (long long)blockIdx.x * blockDim.x + threadIdx.x; i < n;
         i += (long long)gridDim.x * blockDim.x)
        out[i] = 0.f;
}

__global__ void hist_kernel(const void* __restrict__ eidx, int n_edges) {
    const bool is64 = (g_idx_is64 != 0);
    for (int e = blockIdx.x * blockDim.x + threadIdx.x; e < n_edges;
         e += gridDim.x * blockDim.x) {
        int dst = is64 ? (int)((const long long*)eidx)[2 * (size_t)e]
                       : ((const int*)eidx)[2 * (size_t)e];
        atomicAdd(&g_cnt[dst], 1);
    }
}

__global__ void scan1_kernel(int n_nodes) {
    __shared__ int sh[1024];
    int tid = threadIdx.x;
    int i = blockIdx.x * 1024 + tid;
    int v = (i < n_nodes) ? g_cnt[i] : 0;
    sh[tid] = v;
    __syncthreads();
    for (int off = 1; off < 1024; off <<= 1) {
        int t = (tid >= off) ? sh[tid - off] : 0;
        __syncthreads();
        sh[tid] += t;
        __syncthreads();
    }
    if (i < n_nodes) g_scan[i] = sh[tid] - v;
    if (tid == 1023) g_bsum[blockIdx.x] = sh[1023];
}

__global__ void scan2_kernel(int nb) {
    if (threadIdx.x == 0 && blockIdx.x == 0) {
        int s = 0;
        for (int b = 0; b < nb; b++) {
            int t = g_bsum[b];
            g_bsum[b] = s;
            s += t;
        }
    }
}

__global__ void scan3_kernel(int n_nodes) {
    int i = blockIdx.x * blockDim.x + threadIdx.x;
    if (i < n_nodes)
        g_run[i] = g_scan[i] + g_bsum[i >> 10];
}

// ---------------- scatter: build 112B edge records in dst-sorted order ----
__global__ void scatter_kernel(const void* __restrict__ eidx,
                               const float* __restrict__ rbf,
                               const float* __restrict__ env,
                               const float* __restrict__ rij,
                               int n_edges) {
    const bool is64 = (g_idx_is64 != 0);
    for (int e = blockIdx.x * blockDim.x + threadIdx.x; e < n_edges;
         e += gridDim.x * blockDim.x) {
        int dst, j;
        if (is64) {
            const long long* p = (const long long*)eidx;
            dst = (int)p[2 * (size_t)e];
            j = (int)p[2 * (size_t)e + 1];
        } else {
            const int* p = (const int*)eidx;
            dst = p[2 * (size_t)e];
            j = p[2 * (size_t)e + 1];
        }
        int pos = atomicAdd(&g_run[dst], 1);
        float4* row = (float4*)(g_edata + (size_t)pos * EROW);
        float4 a;
        a.x = __int_as_float(j);
        a.y = __int_as_float(dst);
        a.z = env[e];
        a.w = 0.f;
        const float4* rb = (const float4*)(rbf + (size_t)e * R);
        float4 r0 = rb[0], r1 = rb[1], r2 = rb[2], r3 = rb[3], r4 = rb[4];
        float4 b;
        b.x = rij[3 * (size_t)e];
        b.y = rij[3 * (size_t)e + 1];
        b.z = rij[3 * (size_t)e + 2];
        b.w = 0.f;
        row[0] = a; row[1] = r0; row[2] = r1; row[3] = r2;
        row[4] = r3; row[5] = r4; row[6] = b;
    }
}

// ---------------- register-tiled node MLP ----------------
// 64-node tiles. Thread = (cq = tid&15, nq = tid>>4): 4 channels x 4 nodes
// register block, f32x2 packed over node pairs. LDS: 2B/FMA.
#define SMEM_MLP ((64 * 68 + 64 * 196 + 192 + 64 * 66 + 64 * 66) * 4)

__global__ void __launch_bounds__(256)
mlp_kernel(const float* __restrict__ node,
           const float* __restrict__ Ws, const float* __restrict__ bs,
           const float* __restrict__ Wphi, const float* __restrict__ bphi,
           int n_nodes) {
    extern __shared__ float sh[];
    float* sWsT  = sh;                   // [64][68]  k-major
    float* sWpT  = sWsT + 64 * 68;       // [64][196] k-major
    float* sbphi = sWpT + 64 * 196;      // 192
    float* snT   = sbphi + 192;          // [64][66]  k-major node tile
    float* shhT  = snT + 64 * 66;        // [64][66]  k-major hidden tile

    const int tid = threadIdx.x;

    for (int x = tid; x < 64 * 64; x += 256) {
        int cc = x >> 6, k = x & 63;
        sWsT[k * 68 + cc] = Ws[x];
    }
    for (int x = tid; x < 192 * 64; x += 256) {
        int cc = x >> 6, k = x & 63;
        sWpT[k * 196 + cc] = Wphi[x];
    }
    for (int x = tid; x < 192; x += 256) sbphi[x] = bphi[x];

    const int n0 = blockIdx.x * MT;
    for (int x = tid; x < MT * 64; x += 256) {
        int n = x >> 6, k = x & 63;
        snT[k * 66 + n] = (n0 + n < n_nodes) ? node[(size_t)(n0 + n) * 64 + k] : 0.f;
    }
    __syncthreads();

    const int cq = tid & 15, nq = tid >> 4;
    const int cc0 = cq * 4, nn0 = nq * 4;

    // ---- phase 1: h = silu(node @ Ws^T + bs) ----
    {
        ull acc[4][2];
#pragma unroll
        for (int ci = 0; ci < 4; ci++) {
            float b = bs[cc0 + ci];
            acc[ci][0] = pk2(b, b);
            acc[ci][1] = pk2(b, b);
        }
#pragma unroll 8
        for (int k = 0; k < 64; k++) {
            float4 wv = *(const float4*)&sWsT[k * 68 + cc0];
            ull np0 = *(const ull*)&snT[k * 66 + nn0];
            ull np1 = *(const ull*)&snT[k * 66 + nn0 + 2];
            ull w;
            w = pk2(wv.x, wv.x); acc[0][0] = fma2(np0, w, acc[0][0]); acc[0][1] = fma2(np1, w, acc[0][1]);
            w = pk2(wv.y, wv.y); acc[1][0] = fma2(np0, w, acc[1][0]); acc[1][1] = fma2(np1, w, acc[1][1]);
            w = pk2(wv.z, wv.z); acc[2][0] = fma2(np0, w, acc[2][0]); acc[2][1] = fma2(np1, w, acc[2][1]);
            w = pk2(wv.w, wv.w); acc[3][0] = fma2(np0, w, acc[3][0]); acc[3][1] = fma2(np1, w, acc[3][1]);
        }
#pragma unroll
        for (int ci = 0; ci < 4; ci++) {
            float h0, h1, h2, h3;
            upk(acc[ci][0], h0, h1);
            upk(acc[ci][1], h2, h3);
            h0 *= 1.f / (1.f + __expf(-h0));
            h1 *= 1.f / (1.f + __expf(-h1));
            h2 *= 1.f / (1.f + __expf(-h2));
            h3 *= 1.f / (1.f + __expf(-h3));
            *(ull*)&shhT[(cc0 + ci) * 66 + nn0]     = pk2(h0, h1);
            *(ull*)&shhT[(cc0 + ci) * 66 + nn0 + 2] = pk2(h2, h3);
        }
    }
    __syncthreads();

    // ---- phase 2: s = h @ Wphi^T + bphi (3 passes of 64 channels) ----
    for (int p = 0; p < 3; p++) {
        ull acc[4][2];
#pragma unroll
        for (int ci = 0; ci < 4; ci++) {
            float b = sbphi[p * 64 + cc0 + ci];
            acc[ci][0] = pk2(b, b);
            acc[ci][1] = pk2(b, b);
        }
#pragma unroll 8
        for (int k = 0; k < 64; k++) {
            float4 wv = *(const float4*)&sWpT[k * 196 + p * 64 + cc0];
            ull np0 = *(const ull*)&shhT[k * 66 + nn0];
            ull np1 = *(const ull*)&shhT[k * 66 + nn0 + 2];
            ull w;
            w = pk2(wv.x, wv.x); acc[0][0] = fma2(np0, w, acc[0][0]); acc[0][1] = fma2(np1, w, acc[0][1]);
            w = pk2(wv.y, wv.y); acc[1][0] = fma2(np0, w, acc[1][0]); acc[1][1] = fma2(np1, w, acc[1][1]);
            w = pk2(wv.z, wv.z); acc[2][0] = fma2(np0, w, acc[2][0]); acc[2][1] = fma2(np1, w, acc[2][1]);
            w = pk2(wv.w, wv.w); acc[3][0] = fma2(np0, w, acc[3][0]); acc[3][1] = fma2(np1, w, acc[3][1]);
        }
        float sv[4][4];  // [ci][ni]
#pragma unroll
        for (int ci = 0; ci < 4; ci++) {
            upk(acc[ci][0], sv[ci][0], sv[ci][1]);
            upk(acc[ci][1], sv[ci][2], sv[ci][3]);
        }
#pragma unroll
        for (int ni = 0; ni < 4; ni++) {
            int n = n0 + nn0 + ni;
            if (n < n_nodes) {
                float4 v = make_float4(sv[0][ni], sv[1][ni], sv[2][ni], sv[3][ni]);
                *(float4*)&g_s[(size_t)n * S3 + p * 64 + cc0] = v;
            }
        }
    }
}

// ---------------- sweep: dst-sorted ranges with pipelined record staging ----
// Records are linear: staging = 1 LDG.128 + 1 STS.128 per thread per tile,
// prefetched one tile ahead (registers as buffer). 2 barriers / 32 edges.
__global__ void __launch_bounds__(256)
sweep_kernel(const float* __restrict__ Ww, const float* __restrict__ bw,
             const float* __restrict__ equiv,
             float* __restrict__ out_ds, float* __restrict__ out_dv,
             int n_edges) {
    __shared__ __align__(16) float sh_ed[2][CE * EROW];
    __shared__ __align__(16) float sh_sw[CE][S3];

    const int tid  = threadIdx.x;
    const int ch   = tid & 63;
    const int comp = tid >> 6;   // 0..3
    const int c    = tid;        // radial channel if < 192
    const int d    = comp - 1;

    ull wwp[10];
    float bwv = 0.f;
    if (c < S3) {
        const float* wr = Ww + (size_t)c * R;
#pragma unroll
        for (int k = 0; k < 10; k++) wwp[k] = pk2(wr[2 * k], wr[2 * k + 1]);
        bwv = bw[c];
    }

    const int begin = (int)(((long long)n_edges * blockIdx.x) / gridDim.x);
    const int bend  = (int)(((long long)n_edges * (blockIdx.x + 1)) / gridDim.x);
    const int nt    = (bend - begin + CE - 1) / CE;

    int   cur = -1;
    float acc = 0.f;

    // prologue: stage tile 0
    {
        int cnt0 = min(CE, bend - begin);
        if (tid < cnt0 * (EROW / 4)) {
            float4 v = *(const float4*)(g_edata + (size_t)begin * EROW + tid * 4);
            *(float4*)&sh_ed[0][tid * 4] = v;
        }
    }
    __syncthreads();

    for (int ti = 0; ti < nt; ti++) {
        const int tb  = begin + ti * CE;
        const int cnt = min(CE, bend - tb);
        const int buf = ti & 1;

        // prefetch next tile into registers (linear addresses, no deps)
        float4 pre;
        bool havepre = false;
        if (ti + 1 < nt) {
            int nb2 = tb + CE;
            int cnt2 = min(CE, bend - nb2);
            if (tid < cnt2 * (EROW / 4)) {
                pre = *(const float4*)(g_edata + (size_t)nb2 * EROW + tid * 4);
                havepre = true;
            }
        }

        // phase B: sw[el][c] = s[j][c] * ((rbf . Ww_c + bw_c) * env)
        if (c < S3) {
#pragma unroll 4
            for (int el = 0; el < cnt; el++) {
                const float* row = &sh_ed[buf][el * EROW];
                int j = __float_as_int(row[0]);
                float s = g_s[(size_t)j * S3 + c];  // coalesced gather
                const ulonglong2* rb = (const ulonglong2*)(row + 4);
                ull a0 = pk2(bwv, 0.f);
                ull a1 = pk2(0.f, 0.f);
#pragma unroll
                for (int q = 0; q < 5; q++) {
                    ulonglong2 t = rb[q];
                    a0 = fma2(t.x, wwp[2 * q],     a0);
                    a1 = fma2(t.y, wwp[2 * q + 1], a1);
                }
                float w = (upk_sum(a0) + upk_sum(a1)) * row[2];
                sh_sw[el][c] = s * w;
            }
        }
        __syncthreads();

        // phase C: run-carry segmented accumulation
        if (comp == 0) {
#pragma unroll 4
            for (int el = 0; el < cnt; el++) {
                const float* row = &sh_ed[buf][el * EROW];
                int ni = __float_as_int(row[1]);
                if (ni != cur) {
                    if (cur >= 0) red_add(out_ds + (size_t)cur * U + ch, acc);
                    acc = 0.f;
                    cur = ni;
                }
                acc += sh_sw[el][ch];
            }
        } else {
#pragma unroll 4
            for (int el = 0; el < cnt; el++) {
                const float* row = &sh_ed[buf][el * EROW];
                int j = __float_as_int(row[0]);
                float vj = equiv[((size_t)j * 3 + d) * U + ch];  // coalesced
                int ni = __float_as_int(row[1]);
                if (ni != cur) {
                    if (cur >= 0) red_add(out_dv + ((size_t)cur * 3 + d) * U + ch, acc);
                    acc = 0.f;
                    cur = ni;
                }
                acc = fmaf(vj, sh_sw[el][64 + ch],
                           fmaf(row[24 + d], sh_sw[el][128 + ch], acc));
            }
        }

        // store prefetched tile into the other buffer
        if (havepre)
            *(float4*)&sh_ed[buf ^ 1][tid * 4] = pre;
        __syncthreads();
    }

    // final flush
    if (cur >= 0) {
        if (comp == 0) red_add(out_ds + (size_t)cur * U + ch, acc);
        else           red_add(out_dv + ((size_t)cur * 3 + d) * U + ch, acc);
    }
}

// ---------------------------------------------------------------------------
extern "C" void kernel_launch(void* const* d_in, const int* in_sizes, int n_in,
                              void* d_out, int out_size) {
    const float* node  = (const float*)d_in[0];
    const float* equiv = (const float*)d_in[1];
    const float* rbf   = (const float*)d_in[2];
    const float* env   = (const float*)d_in[3];
    const float* rij   = (const float*)d_in[4];
    const void*  eidx  = d_in[5];
    const float* Ws    = (const float*)d_in[6];
    const float* bs    = (const float*)d_in[7];
    const float* Wphi  = (const float*)d_in[8];
    const float* bphi  = (const float*)d_in[9];
    const float* Ww    = (const float*)d_in[10];
    const float* bw    = (const float*)d_in[11];

    int n_nodes = in_sizes[0] / U;
    int n_edges = in_sizes[3];

    float* out_ds = (float*)d_out;
    float* out_dv = out_ds + (size_t)n_nodes * U;

    int nb_scan = (n_nodes + 1023) / 1024;

    detect_idx_kernel<<<1, 256>>>((const int*)eidx, n_edges);
    zero_cnt_kernel<<<(n_nodes + 255) / 256, 256>>>(n_nodes);
    zero_out_kernel<<<592, 256>>>((float*)d_out, (long long)out_size);

    cudaFuncSetAttribute(mlp_kernel, cudaFuncAttributeMaxDynamicSharedMemorySize, SMEM_MLP);
    mlp_kernel<<<(n_nodes + MT - 1) / MT, 256, SMEM_MLP>>>(node, Ws, bs, Wphi, bphi, n_nodes);

    hist_kernel<<<400, 256>>>(eidx, n_edges);
    scan1_kernel<<<nb_scan, 1024>>>(n_nodes);
    scan2_kernel<<<1, 32>>>(nb_scan);
    scan3_kernel<<<(n_nodes + 1023) / 1024, 1024>>>(n_nodes);
    scatter_kernel<<<400, 256>>>(eidx, rbf, env, rij, n_edges);

    sweep_kernel<<<NB, 256>>>(Ww, bw, equiv, out_ds, out_dv, n_edges);
}